// round 1
// baseline (speedup 1.0000x reference)
#include <cuda_runtime.h>

#define BB 8
#define DD 128
#define TT 32768
#define CC 64

// ---------------- scratch (static device globals; no allocation) ----------------
__device__ float g_G[BB * DD * DD];     // per-batch Gram matrices
__device__ float g_s[BB * DD];          // per-batch row sums of x over t
__device__ float g_Bm[CC * DD];         // we @ wk
__device__ float g_F[CC * DD];          // wf @ wv
__device__ float g_k0[CC];              // we @ bk + be
__device__ float g_v0[CC];              // wf @ bv + bf
__device__ float g_wot[CC * DD];        // wo transposed: [c][o]
__device__ float g_AG[BB * CC * DD];    // wq @ G_b
__device__ float g_Mt[BB * DD * CC];    // M_b transposed: [b][d][c]
__device__ float g_cv[BB * CC];         // P_b @ v0

// ================= K1: per-batch Gram (G = x x^T) + row sums =================
// grid (128, 8), 256 threads. Each block: 256 t-columns, full 128x128 Gram tile,
// atomically accumulated into g_G. Shared tile stored transposed [t][d] (pad 132)
// so compute-phase fragments are float4-contiguous.
__global__ __launch_bounds__(256, 2) void k1_gram(const float* __restrict__ x) {
    __shared__ float xs[32][132];
    const int b   = blockIdx.y;
    const int t0  = blockIdx.x * 256;
    const int tid = threadIdx.x;
    const int ty  = tid >> 4;   // 0..15
    const int tx  = tid & 15;   // 0..15
    const float* xb = x + (size_t)b * DD * TT;

    float acc[8][8];
#pragma unroll
    for (int i = 0; i < 8; i++)
#pragma unroll
        for (int j = 0; j < 8; j++) acc[i][j] = 0.f;
    float srow[4] = {0.f, 0.f, 0.f, 0.f};

    for (int kt = 0; kt < 8; kt++) {
        const int tb = t0 + kt * 32;
#pragma unroll
        for (int m = 0; m < 4; m++) {
            int flat = tid + 256 * m;
            int d    = flat >> 3;           // 0..127
            int tl   = (flat & 7) << 2;     // 0,4,...,28
            float4 v = *reinterpret_cast<const float4*>(xb + (size_t)d * TT + tb + tl);
            srow[m] += (v.x + v.y) + (v.z + v.w);
            xs[tl + 0][d] = v.x; xs[tl + 1][d] = v.y;
            xs[tl + 2][d] = v.z; xs[tl + 3][d] = v.w;
        }
        __syncthreads();
#pragma unroll
        for (int k = 0; k < 32; k++) {
            float4 a0 = *reinterpret_cast<const float4*>(&xs[k][ty * 8]);
            float4 a1 = *reinterpret_cast<const float4*>(&xs[k][ty * 8 + 4]);
            float4 b0 = *reinterpret_cast<const float4*>(&xs[k][tx * 8]);
            float4 b1 = *reinterpret_cast<const float4*>(&xs[k][tx * 8 + 4]);
            float a[8]  = {a0.x, a0.y, a0.z, a0.w, a1.x, a1.y, a1.z, a1.w};
            float bv[8] = {b0.x, b0.y, b0.z, b0.w, b1.x, b1.y, b1.z, b1.w};
#pragma unroll
            for (int i = 0; i < 8; i++)
#pragma unroll
                for (int j = 0; j < 8; j++)
                    acc[i][j] = fmaf(a[i], bv[j], acc[i][j]);
        }
        __syncthreads();
    }

    float* Gb = g_G + b * DD * DD;
#pragma unroll
    for (int i = 0; i < 8; i++)
#pragma unroll
        for (int j = 0; j < 8; j++)
            atomicAdd(&Gb[(ty * 8 + i) * DD + tx * 8 + j], acc[i][j]);
#pragma unroll
    for (int m = 0; m < 4; m++)
        atomicAdd(&g_s[b * DD + (tid >> 3) + 32 * m], srow[m]);
}

// ============ K2a: batch-independent weight products (grid 16) ============
__global__ void k2a_weights(const float* __restrict__ we, const float* __restrict__ wk,
                            const float* __restrict__ bk, const float* __restrict__ be,
                            const float* __restrict__ wf, const float* __restrict__ wv,
                            const float* __restrict__ bv, const float* __restrict__ bf,
                            const float* __restrict__ wo) {
    const int j = blockIdx.x, tid = threadIdx.x;
    if (j < 8) {
#pragma unroll
        for (int it = 0; it < 4; it++) {
            int idx = tid + 256 * it;
            int o = j * 8 + (idx >> 7);
            int d = idx & 127;
            float acc = 0.f;
            for (int c = 0; c < CC; c++) acc = fmaf(we[o * CC + c], wk[c * DD + d], acc);
            g_Bm[o * DD + d] = acc;
        }
        if (j == 0 && tid < CC) {
            float acc = be[tid];
            for (int c = 0; c < CC; c++) acc = fmaf(we[tid * CC + c], bk[c], acc);
            g_k0[tid] = acc;
        }
        if (j == 1) {
#pragma unroll
            for (int it = 0; it < 32; it++) {
                int idx = tid + 256 * it;
                int c = idx >> 7, o = idx & 127;
                g_wot[c * DD + o] = wo[o * CC + c];
            }
        }
    } else {
        int jj = j - 8;
#pragma unroll
        for (int it = 0; it < 4; it++) {
            int idx = tid + 256 * it;
            int o = jj * 8 + (idx >> 7);
            int d = idx & 127;
            float acc = 0.f;
            for (int c = 0; c < CC; c++) acc = fmaf(wf[o * CC + c], wv[c * DD + d], acc);
            g_F[o * DD + d] = acc;
        }
        if (j == 8 && tid < CC) {
            float acc = bf[tid];
            for (int c = 0; c < CC; c++) acc = fmaf(wf[tid * CC + c], bv[c], acc);
            g_v0[tid] = acc;
        }
    }
}

// ============ K2b: AG_b = wq @ G_b  (grid (4,8)) ============
__global__ void k2b_ag(const float* __restrict__ wq) {
    const int b = blockIdx.y, bx = blockIdx.x, tid = threadIdx.x;
    const float* Gb = g_G + b * DD * DD;
#pragma unroll
    for (int it = 0; it < 8; it++) {
        int idx = tid + 256 * it;
        int c  = idx >> 5;
        int d  = bx * 32 + (idx & 31);
        float acc = 0.f;
        for (int d1 = 0; d1 < DD; d1++)
            acc = fmaf(wq[c * DD + d1], Gb[d1 * DD + d], acc);
        g_AG[b * CC * DD + c * DD + d] = acc;
    }
}

// ============ K2c: S, softmax, M_b, c_b  (grid 8, dyn smem) ============
__global__ void k2c_attn(const float* __restrict__ wq, const float* __restrict__ bq) {
    extern __shared__ float sm2[];
    float* AGs = sm2;                    // CC*DD
    float* Bms = AGs + CC * DD;          // CC*129 (pad -> conflict-free column reads)
    float* Fs  = Bms + CC * 129;         // CC*DD
    float* Ps  = Fs + CC * DD;           // CC*CC
    float* ss  = Ps + CC * CC;           // DD
    float* qs  = ss + DD;                // CC
    float* bs  = qs + CC;                // CC
    float* k0s = bs + CC;                // CC
    float* v0s = k0s + CC;               // CC
    const int b = blockIdx.x, tid = threadIdx.x;

    for (int i = tid; i < CC * DD; i += 256) AGs[i] = g_AG[b * CC * DD + i];
    for (int i = tid; i < CC * DD; i += 256) {
        int k = i >> 7, d = i & 127;
        Bms[k * 129 + d] = g_Bm[i];
    }
    for (int i = tid; i < CC * DD; i += 256) Fs[i] = g_F[i];
    if (tid < DD) ss[tid] = g_s[b * DD + tid];
    if (tid < CC) { k0s[tid] = g_k0[tid]; v0s[tid] = g_v0[tid]; }
    __syncthreads();

    if (tid < CC) {
        float a = 0.f;
        for (int d = 0; d < DD; d++) a = fmaf(wq[tid * DD + d], ss[d], a);
        qs[tid] = a;
    } else if (tid < 2 * CC) {
        int k = tid - CC;
        float a = 0.f;
        for (int d = 0; d < DD; d++) a = fmaf(Bms[k * 129 + d], ss[d], a);
        bs[k] = a;
    }
    __syncthreads();

    // S[c][k] (scaled logits stored into Ps)
    {
        const int k = tid & 63;
        const int c0 = tid >> 6;
        const float k0v = k0s[k], bsv = bs[k];
#pragma unroll
        for (int i = 0; i < 16; i++) {
            int c = c0 + 4 * i;
            float acc = 0.f;
            const float* ag = &AGs[c * DD];
            const float* bm = &Bms[k * 129];
            for (int d = 0; d < DD; d++) acc = fmaf(ag[d], bm[d], acc);
            float bqc = bq[c];
            acc += qs[c] * k0v + bqc * bsv + (float)TT * bqc * k0v;
            Ps[c * CC + k] = acc * 0.125f;   // /sqrt(64)
        }
    }
    __syncthreads();

    // softmax over rows (warp handles 8 rows)
    {
        const int w = tid >> 5, lane = tid & 31;
        for (int r = w * 8; r < w * 8 + 8; r++) {
            float v0 = Ps[r * CC + lane], v1 = Ps[r * CC + lane + 32];
            float m = fmaxf(v0, v1);
#pragma unroll
            for (int off = 16; off; off >>= 1) m = fmaxf(m, __shfl_xor_sync(~0u, m, off));
            float e0 = expf(v0 - m), e1 = expf(v1 - m);
            float sum = e0 + e1;
#pragma unroll
            for (int off = 16; off; off >>= 1) sum += __shfl_xor_sync(~0u, sum, off);
            float inv = 1.f / sum;
            Ps[r * CC + lane]      = e0 * inv;
            Ps[r * CC + lane + 32] = e1 * inv;
        }
    }
    __syncthreads();

    // Mt[d][c] = sum_k P[c][k] F[k][d];  cv[c] = sum_k P[c][k] v0[k]
    {
        const int d = tid & 127, c0 = tid >> 7;
#pragma unroll
        for (int i = 0; i < 32; i++) {
            int c = c0 + 2 * i;
            float acc = 0.f;
            for (int k = 0; k < CC; k++) acc = fmaf(Ps[c * CC + k], Fs[k * DD + d], acc);
            g_Mt[b * DD * CC + d * CC + c] = acc;
        }
    }
    if (tid < CC) {
        float acc = 0.f;
        for (int k = 0; k < CC; k++) acc = fmaf(Ps[tid * CC + k], v0s[k], acc);
        g_cv[b * CC + tid] = acc;
    }
}

// ============ K3: y = mask * (wo @ relu(M x + c) + bo)  (grid (256,8)) ============
__global__ __launch_bounds__(256, 1) void k3_out(const float* __restrict__ x,
                                                 const float* __restrict__ mask,
                                                 const float* __restrict__ bo,
                                                 float* __restrict__ y) {
    extern __shared__ float sm3[];
    float* Xs  = sm3;               // 128 x 128  (X[d][t])
    float* Us  = Xs + DD * 128;     //  64 x 128  (relu(Mx+c))
    float* Mts = Us + CC * 128;     // 128 x 64   (M transposed: [d][c])
    float* Wts = Mts + DD * CC;     //  64 x 128  (wo transposed: [c][o])
    const int b   = blockIdx.y;
    const int t0  = blockIdx.x * 128;
    const int tid = threadIdx.x;

    {
        const float4* src = reinterpret_cast<const float4*>(g_Mt + b * DD * CC);
        float4* dst = reinterpret_cast<float4*>(Mts);
#pragma unroll
        for (int i = 0; i < 8; i++) dst[tid + 256 * i] = src[tid + 256 * i];
    }
    {
        const float4* src = reinterpret_cast<const float4*>(g_wot);
        float4* dst = reinterpret_cast<float4*>(Wts);
#pragma unroll
        for (int i = 0; i < 8; i++) dst[tid + 256 * i] = src[tid + 256 * i];
    }
    {
        const float* xb = x + (size_t)b * DD * TT + t0;
#pragma unroll
        for (int i = 0; i < 16; i++) {
            int f4 = tid + 256 * i;
            int d  = f4 >> 5;
            int tl = (f4 & 31) << 2;
            *reinterpret_cast<float4*>(&Xs[d * 128 + tl]) =
                *reinterpret_cast<const float4*>(xb + (size_t)d * TT + tl);
        }
    }
    __syncthreads();

    // Step A: U = relu(M X + c). 8x32 thread grid, 8x4 thread tile.
    {
        const int ty = tid >> 5, tx = tid & 31;
        float acc[8][4];
#pragma unroll
        for (int i = 0; i < 8; i++)
#pragma unroll
            for (int j = 0; j < 4; j++) acc[i][j] = 0.f;
        for (int k = 0; k < DD; k++) {
            float4 a0 = *reinterpret_cast<const float4*>(&Mts[k * CC + ty * 8]);
            float4 a1 = *reinterpret_cast<const float4*>(&Mts[k * CC + ty * 8 + 4]);
            float4 bv = *reinterpret_cast<const float4*>(&Xs[k * 128 + tx * 4]);
            float a[8]  = {a0.x, a0.y, a0.z, a0.w, a1.x, a1.y, a1.z, a1.w};
            float bb[4] = {bv.x, bv.y, bv.z, bv.w};
#pragma unroll
            for (int i = 0; i < 8; i++)
#pragma unroll
                for (int j = 0; j < 4; j++)
                    acc[i][j] = fmaf(a[i], bb[j], acc[i][j]);
        }
#pragma unroll
        for (int i = 0; i < 8; i++) {
            float cvv = g_cv[b * CC + ty * 8 + i];
#pragma unroll
            for (int j = 0; j < 4; j++)
                Us[(ty * 8 + i) * 128 + tx * 4 + j] = fmaxf(acc[i][j] + cvv, 0.f);
        }
    }
    __syncthreads();

    // Step B: Y = wo U + bo, masked. 16x16 thread grid, 8x8 tile.
    {
        const int ty = tid >> 4, tx = tid & 15;
        float acc[8][8];
#pragma unroll
        for (int i = 0; i < 8; i++)
#pragma unroll
            for (int j = 0; j < 8; j++) acc[i][j] = 0.f;
        for (int k = 0; k < CC; k++) {
            float4 a0 = *reinterpret_cast<const float4*>(&Wts[k * 128 + ty * 8]);
            float4 a1 = *reinterpret_cast<const float4*>(&Wts[k * 128 + ty * 8 + 4]);
            float4 b0 = *reinterpret_cast<const float4*>(&Us[k * 128 + tx * 8]);
            float4 b1 = *reinterpret_cast<const float4*>(&Us[k * 128 + tx * 8 + 4]);
            float a[8]  = {a0.x, a0.y, a0.z, a0.w, a1.x, a1.y, a1.z, a1.w};
            float bb[8] = {b0.x, b0.y, b0.z, b0.w, b1.x, b1.y, b1.z, b1.w};
#pragma unroll
            for (int i = 0; i < 8; i++)
#pragma unroll
                for (int j = 0; j < 8; j++)
                    acc[i][j] = fmaf(a[i], bb[j], acc[i][j]);
        }
        float* yb = y + (size_t)b * DD * TT + t0;
        const float* mb = mask + (size_t)b * TT + t0;
        float4 m0 = *reinterpret_cast<const float4*>(&mb[tx * 8]);
        float4 m1 = *reinterpret_cast<const float4*>(&mb[tx * 8 + 4]);
        float mv[8] = {m0.x, m0.y, m0.z, m0.w, m1.x, m1.y, m1.z, m1.w};
#pragma unroll
        for (int i = 0; i < 8; i++) {
            float bov = bo[ty * 8 + i];
            float4 o0, o1;
            o0.x = (acc[i][0] + bov) * mv[0];
            o0.y = (acc[i][1] + bov) * mv[1];
            o0.z = (acc[i][2] + bov) * mv[2];
            o0.w = (acc[i][3] + bov) * mv[3];
            o1.x = (acc[i][4] + bov) * mv[4];
            o1.y = (acc[i][5] + bov) * mv[5];
            o1.z = (acc[i][6] + bov) * mv[6];
            o1.w = (acc[i][7] + bov) * mv[7];
            float* row = &yb[(size_t)(ty * 8 + i) * TT + tx * 8];
            *reinterpret_cast<float4*>(row)     = o0;
            *reinterpret_cast<float4*>(row + 4) = o1;
        }
    }
}

static const int SMEM_K2C = (CC * DD + CC * 129 + CC * DD + CC * CC + DD + 4 * CC) * (int)sizeof(float);
static const int SMEM_K3  = (DD * 128 + CC * 128 + DD * CC + CC * DD) * (int)sizeof(float);

extern "C" void kernel_launch(void* const* d_in, const int* in_sizes, int n_in,
                              void* d_out, int out_size) {
    const float* x1   = (const float*)d_in[0];
    // d_in[1] = x2 (unused in encoder stage)
    const float* mask = (const float*)d_in[2];
    const float* wq   = (const float*)d_in[3];
    const float* bq   = (const float*)d_in[4];
    const float* wk   = (const float*)d_in[5];
    const float* bk   = (const float*)d_in[6];
    const float* wv   = (const float*)d_in[7];
    const float* bv   = (const float*)d_in[8];
    const float* we   = (const float*)d_in[9];
    const float* be   = (const float*)d_in[10];
    const float* wf   = (const float*)d_in[11];
    const float* bf   = (const float*)d_in[12];
    const float* wo   = (const float*)d_in[13];
    const float* bo   = (const float*)d_in[14];
    float* y = (float*)d_out;

    cudaFuncSetAttribute(k2c_attn, cudaFuncAttributeMaxDynamicSharedMemorySize, SMEM_K2C);
    cudaFuncSetAttribute(k3_out,   cudaFuncAttributeMaxDynamicSharedMemorySize, SMEM_K3);

    void *pG = nullptr, *ps = nullptr;
    cudaGetSymbolAddress(&pG, g_G);
    cudaGetSymbolAddress(&ps, g_s);
    cudaMemsetAsync(pG, 0, BB * DD * DD * sizeof(float));
    cudaMemsetAsync(ps, 0, BB * DD * sizeof(float));

    k1_gram<<<dim3(128, 8), 256>>>(x1);
    k2a_weights<<<16, 256>>>(we, wk, bk, be, wf, wv, bv, bf, wo);
    k2b_ag<<<dim3(4, 8), 256>>>(wq);
    k2c_attn<<<8, 256, SMEM_K2C>>>(wq, bq);
    k3_out<<<dim3(256, 8), 256, SMEM_K3>>>(x1, mask, bo, y);
}

// round 2
// speedup vs baseline: 1.2556x; 1.2556x over previous
#include <cuda_runtime.h>

#define BB 8
#define DD 128
#define TT 32768
#define CC 64

typedef unsigned long long ull;

// ---------------- f32x2 packed-FMA helpers (sm_103a FFMA2 path) ----------------
__device__ __forceinline__ void ffma2(ull& d, ull a, ull b) {
    asm("fma.rn.f32x2 %0, %1, %2, %0;" : "+l"(d) : "l"(a), "l"(b));
}
__device__ __forceinline__ ull pk2(float lo, float hi) {
    ull r; asm("mov.b64 %0, {%1, %2};" : "=l"(r) : "f"(lo), "f"(hi)); return r;
}
__device__ __forceinline__ float2 upk(ull v) {
    float2 r; asm("mov.b64 {%0, %1}, %2;" : "=f"(r.x), "=f"(r.y) : "l"(v)); return r;
}
__device__ __forceinline__ ull add2(ull a, ull b) {
    ull r; asm("add.rn.f32x2 %0, %1, %2;" : "=l"(r) : "l"(a), "l"(b)); return r;
}
__device__ __forceinline__ ull mul2(ull a, ull b) {
    ull r; asm("mul.rn.f32x2 %0, %1, %2;" : "=l"(r) : "l"(a), "l"(b)); return r;
}

// ---------------- scratch (static device globals; no allocation) ----------------
__device__ float g_G[BB * DD * DD];     // per-batch Gram matrices
__device__ float g_s[BB * DD];          // per-batch row sums of x over t
__device__ float g_Bm[CC * DD];         // we @ wk
__device__ float g_F[CC * DD];          // wf @ wv
__device__ float g_k0[CC];              // we @ bk + be
__device__ float g_v0[CC];              // wf @ bv + bf
__device__ float g_wot[CC * DD];        // wo transposed: [c][o]
__device__ float g_Mt[BB * DD * CC];    // M_b transposed: [b][d][c]
__device__ float g_cv[BB * CC];         // P_b @ v0

// ================= K1: per-batch Gram (G = x x^T) + row sums =================
// grid (32, 8), 256 threads. Each block: 1024 t-columns. FFMA2 inner loop:
// acc pairs packed along j (b-side natural pairs), a broadcast-dup per i.
__global__ __launch_bounds__(256, 2) void k1_gram(const float* __restrict__ x) {
    __shared__ float xs[32][132];
    const int b   = blockIdx.y;
    const int t0  = blockIdx.x * 1024;
    const int tid = threadIdx.x;
    const int ty  = tid >> 4;   // 0..15
    const int tx  = tid & 15;   // 0..15
    const float* xb = x + (size_t)b * DD * TT;

    ull acc[8][4];
#pragma unroll
    for (int i = 0; i < 8; i++)
#pragma unroll
        for (int j = 0; j < 4; j++) acc[i][j] = 0ull;
    float srow[4] = {0.f, 0.f, 0.f, 0.f};

    for (int kt = 0; kt < 32; kt++) {
        const int tb = t0 + kt * 32;
#pragma unroll
        for (int m = 0; m < 4; m++) {
            int flat = tid + 256 * m;
            int d    = flat >> 3;           // 0..127
            int tl   = (flat & 7) << 2;     // 0,4,...,28
            float4 v = *reinterpret_cast<const float4*>(xb + (size_t)d * TT + tb + tl);
            srow[m] += (v.x + v.y) + (v.z + v.w);
            xs[tl + 0][d] = v.x; xs[tl + 1][d] = v.y;
            xs[tl + 2][d] = v.z; xs[tl + 3][d] = v.w;
        }
        __syncthreads();
#pragma unroll 8
        for (int k = 0; k < 32; k++) {
            float4 a0 = *reinterpret_cast<const float4*>(&xs[k][ty * 8]);
            float4 a1 = *reinterpret_cast<const float4*>(&xs[k][ty * 8 + 4]);
            float4 b0 = *reinterpret_cast<const float4*>(&xs[k][tx * 8]);
            float4 b1 = *reinterpret_cast<const float4*>(&xs[k][tx * 8 + 4]);
            ull bp0 = pk2(b0.x, b0.y), bp1 = pk2(b0.z, b0.w);
            ull bp2 = pk2(b1.x, b1.y), bp3 = pk2(b1.z, b1.w);
            float av[8] = {a0.x, a0.y, a0.z, a0.w, a1.x, a1.y, a1.z, a1.w};
#pragma unroll
            for (int i = 0; i < 8; i++) {
                ull ad = pk2(av[i], av[i]);
                ffma2(acc[i][0], ad, bp0);
                ffma2(acc[i][1], ad, bp1);
                ffma2(acc[i][2], ad, bp2);
                ffma2(acc[i][3], ad, bp3);
            }
        }
        __syncthreads();
    }

    float* Gb = g_G + b * DD * DD;
#pragma unroll
    for (int i = 0; i < 8; i++)
#pragma unroll
        for (int j = 0; j < 4; j++) {
            float2 v = upk(acc[i][j]);
            atomicAdd(&Gb[(ty * 8 + i) * DD + tx * 8 + 2 * j],     v.x);
            atomicAdd(&Gb[(ty * 8 + i) * DD + tx * 8 + 2 * j + 1], v.y);
        }
#pragma unroll
    for (int m = 0; m < 4; m++)
        atomicAdd(&g_s[b * DD + (tid >> 3) + 32 * m], srow[m]);
}

// ============ K2a: batch-independent weight products (grid 16) ============
__global__ void k2a_weights(const float* __restrict__ we, const float* __restrict__ wk,
                            const float* __restrict__ bk, const float* __restrict__ be,
                            const float* __restrict__ wf, const float* __restrict__ wv,
                            const float* __restrict__ bv, const float* __restrict__ bf,
                            const float* __restrict__ wo) {
    const int j = blockIdx.x, tid = threadIdx.x;
    if (j < 8) {
#pragma unroll
        for (int it = 0; it < 4; it++) {
            int idx = tid + 256 * it;
            int o = j * 8 + (idx >> 7);
            int d = idx & 127;
            float acc = 0.f;
            for (int c = 0; c < CC; c++) acc = fmaf(we[o * CC + c], wk[c * DD + d], acc);
            g_Bm[o * DD + d] = acc;
        }
        if (j == 0 && tid < CC) {
            float acc = be[tid];
            for (int c = 0; c < CC; c++) acc = fmaf(we[tid * CC + c], bk[c], acc);
            g_k0[tid] = acc;
        }
        if (j == 1) {
#pragma unroll
            for (int it = 0; it < 32; it++) {
                int idx = tid + 256 * it;
                int c = idx >> 7, o = idx & 127;
                g_wot[c * DD + o] = wo[o * CC + c];
            }
        }
    } else {
        int jj = j - 8;
#pragma unroll
        for (int it = 0; it < 4; it++) {
            int idx = tid + 256 * it;
            int o = jj * 8 + (idx >> 7);
            int d = idx & 127;
            float acc = 0.f;
            for (int c = 0; c < CC; c++) acc = fmaf(wf[o * CC + c], wv[c * DD + d], acc);
            g_F[o * DD + d] = acc;
        }
        if (j == 8 && tid < CC) {
            float acc = bf[tid];
            for (int c = 0; c < CC; c++) acc = fmaf(wf[tid * CC + c], bv[c], acc);
            g_v0[tid] = acc;
        }
    }
}

// ============ K2c: AG + S + softmax + M + cv, fused. grid (8 c-groups, 8 b) ============
// Each block owns 8 attention rows c = cg*8..cg*8+7 (softmax rows are independent).
// Uses G symmetry: AG[c,d] = sum_d1 G[d][d1] * wq[c][d1] (row-major reads).
#define KPAD 132
__global__ void k2c_attn(const float* __restrict__ wq, const float* __restrict__ bq) {
    extern __shared__ float sm2[];
    float* Gs  = sm2;                  // 128 x KPAD
    float* Bms = Gs  + DD * KPAD;      //  64 x KPAD
    float* Fs  = Bms + CC * KPAD;      //  64 x KPAD
    float* wqs = Fs  + CC * KPAD;      //   8 x KPAD
    float* AGs = wqs + 8 * KPAD;       //   8 x KPAD
    float* Ps  = AGs + 8 * KPAD;       //   8 x 64
    float* ss  = Ps  + 8 * CC;         // 128
    float* bs  = ss  + DD;             //  64
    float* k0s = bs  + CC;             //  64
    float* v0s = k0s + CC;             //  64
    float* qs  = v0s + CC;             //   8
    float* bqs = qs  + 8;              //   8
    const int cg = blockIdx.x, b = blockIdx.y, tid = threadIdx.x;

    // ---- cooperative loads (float4 granularity) ----
    const float* Gb = g_G + b * DD * DD;
    for (int i = tid; i < DD * 32; i += 256) {
        int r = i >> 5, c4 = (i & 31) << 2;
        *reinterpret_cast<float4*>(&Gs[r * KPAD + c4]) =
            *reinterpret_cast<const float4*>(&Gb[r * DD + c4]);
    }
    for (int i = tid; i < CC * 32; i += 256) {
        int r = i >> 5, c4 = (i & 31) << 2;
        *reinterpret_cast<float4*>(&Bms[r * KPAD + c4]) =
            *reinterpret_cast<const float4*>(&g_Bm[r * DD + c4]);
        *reinterpret_cast<float4*>(&Fs[r * KPAD + c4]) =
            *reinterpret_cast<const float4*>(&g_F[r * DD + c4]);
    }
    for (int i = tid; i < 8 * 32; i += 256) {
        int r = i >> 5, c4 = (i & 31) << 2;
        *reinterpret_cast<float4*>(&wqs[r * KPAD + c4]) =
            *reinterpret_cast<const float4*>(&wq[(cg * 8 + r) * DD + c4]);
    }
    if (tid < DD) ss[tid] = g_s[b * DD + tid];
    if (tid < CC) { k0s[tid] = g_k0[tid]; v0s[tid] = g_v0[tid]; }
    if (tid < 8)  bqs[tid] = bq[cg * 8 + tid];
    __syncthreads();

    // ---- bs[k] = Bm_row_k . s ; qs[ci] = wq_row_c . s ----
    if (tid < CC) {
        float a = 0.f;
        const float* r = &Bms[tid * KPAD];
        for (int d = 0; d < DD; d++) a = fmaf(r[d], ss[d], a);
        bs[tid] = a;
    } else if (tid < CC + 8) {
        int ci = tid - CC;
        float a = 0.f;
        const float* r = &wqs[ci * KPAD];
        for (int d = 0; d < DD; d++) a = fmaf(r[d], ss[d], a);
        qs[ci] = a;
    }
    // ---- AG rows: AGs[ci][d] = sum_d1 Gs[d1][d] * wqs[ci][d1] (G symmetric) ----
    {
        const int d = tid >> 1, cb = (tid & 1) * 4;
        float a0 = 0.f, a1 = 0.f, a2 = 0.f, a3 = 0.f;
        for (int d1 = 0; d1 < DD; d1++) {
            float g = Gs[d1 * KPAD + d];
            a0 = fmaf(g, wqs[(cb + 0) * KPAD + d1], a0);
            a1 = fmaf(g, wqs[(cb + 1) * KPAD + d1], a1);
            a2 = fmaf(g, wqs[(cb + 2) * KPAD + d1], a2);
            a3 = fmaf(g, wqs[(cb + 3) * KPAD + d1], a3);
        }
        AGs[(cb + 0) * KPAD + d] = a0;
        AGs[(cb + 1) * KPAD + d] = a1;
        AGs[(cb + 2) * KPAD + d] = a2;
        AGs[(cb + 3) * KPAD + d] = a3;
    }
    __syncthreads();

    // ---- S logits (scaled) ----
    {
        const int ci = tid >> 5, k = tid & 31;
#pragma unroll
        for (int rep = 0; rep < 2; rep++) {
            int kk = k + rep * 32;
            float acc = 0.f;
            for (int d4 = 0; d4 < 32; d4++) {
                float4 ag = *reinterpret_cast<const float4*>(&AGs[ci * KPAD + d4 * 4]);
                float4 bm = *reinterpret_cast<const float4*>(&Bms[kk * KPAD + d4 * 4]);
                acc = fmaf(ag.x, bm.x, acc); acc = fmaf(ag.y, bm.y, acc);
                acc = fmaf(ag.z, bm.z, acc); acc = fmaf(ag.w, bm.w, acc);
            }
            acc += qs[ci] * k0s[kk] + bqs[ci] * bs[kk] + (float)TT * bqs[ci] * k0s[kk];
            Ps[ci * CC + kk] = acc * 0.125f;  // /sqrt(64)
        }
    }
    __syncthreads();

    // ---- softmax per row (warp w owns row w) ----
    {
        const int w = tid >> 5, lane = tid & 31;
        float v0 = Ps[w * CC + lane], v1 = Ps[w * CC + lane + 32];
        float m = fmaxf(v0, v1);
#pragma unroll
        for (int off = 16; off; off >>= 1) m = fmaxf(m, __shfl_xor_sync(~0u, m, off));
        float e0 = expf(v0 - m), e1 = expf(v1 - m);
        float sum = e0 + e1;
#pragma unroll
        for (int off = 16; off; off >>= 1) sum += __shfl_xor_sync(~0u, sum, off);
        float inv = 1.f / sum;
        Ps[w * CC + lane]      = e0 * inv;
        Ps[w * CC + lane + 32] = e1 * inv;
    }
    __syncthreads();

    // ---- Mt[d][c] = sum_k P[c][k] F[k][d];  cv[c] = sum_k P[c][k] v0[k] ----
    {
        const int d = tid >> 1, cb = (tid & 1) * 4;
        float a0 = 0.f, a1 = 0.f, a2 = 0.f, a3 = 0.f;
        for (int k = 0; k < CC; k++) {
            float f = Fs[k * KPAD + d];
            a0 = fmaf(Ps[(cb + 0) * CC + k], f, a0);
            a1 = fmaf(Ps[(cb + 1) * CC + k], f, a1);
            a2 = fmaf(Ps[(cb + 2) * CC + k], f, a2);
            a3 = fmaf(Ps[(cb + 3) * CC + k], f, a3);
        }
        float4 o = {a0, a1, a2, a3};
        *reinterpret_cast<float4*>(&g_Mt[b * DD * CC + d * CC + cg * 8 + cb]) = o;
    }
    if (tid < 8) {
        float acc = 0.f;
        for (int k = 0; k < CC; k++) acc = fmaf(Ps[tid * CC + k], v0s[k], acc);
        g_cv[b * CC + cg * 8 + tid] = acc;
    }
}

// ============ K3: y = mask * (wo @ relu(M x + c) + bo)  (grid (256,8)) ============
__global__ __launch_bounds__(256, 1) void k3_out(const float* __restrict__ x,
                                                 const float* __restrict__ mask,
                                                 const float* __restrict__ bo,
                                                 float* __restrict__ y) {
    extern __shared__ float sm3[];
    float* Xs  = sm3;               // 128 x 128  (X[d][t])
    float* Us  = Xs + DD * 128;     //  64 x 128  (relu(Mx+c))
    float* Mts = Us + CC * 128;     // 128 x 64   (M transposed: [d][c])
    float* Wts = Mts + DD * CC;     //  64 x 128  (wo transposed: [c][o])
    const int b   = blockIdx.y;
    const int t0  = blockIdx.x * 128;
    const int tid = threadIdx.x;

    {
        const float4* src = reinterpret_cast<const float4*>(g_Mt + b * DD * CC);
        float4* dst = reinterpret_cast<float4*>(Mts);
#pragma unroll
        for (int i = 0; i < 8; i++) dst[tid + 256 * i] = src[tid + 256 * i];
    }
    {
        const float4* src = reinterpret_cast<const float4*>(g_wot);
        float4* dst = reinterpret_cast<float4*>(Wts);
#pragma unroll
        for (int i = 0; i < 8; i++) dst[tid + 256 * i] = src[tid + 256 * i];
    }
    {
        const float* xb = x + (size_t)b * DD * TT + t0;
#pragma unroll
        for (int i = 0; i < 16; i++) {
            int f4 = tid + 256 * i;
            int d  = f4 >> 5;
            int tl = (f4 & 31) << 2;
            *reinterpret_cast<float4*>(&Xs[d * 128 + tl]) =
                *reinterpret_cast<const float4*>(xb + (size_t)d * TT + tl);
        }
    }
    __syncthreads();

    // Step A: U = relu(M X + c). 8x32 thread grid, tile 8c x 4t, acc packed along c.
    {
        const int ty = tid >> 5, tx = tid & 31;
        ull acc[4][4];
#pragma unroll
        for (int i = 0; i < 4; i++)
#pragma unroll
            for (int j = 0; j < 4; j++) acc[i][j] = 0ull;
#pragma unroll 8
        for (int k = 0; k < DD; k++) {
            float4 m0 = *reinterpret_cast<const float4*>(&Mts[k * CC + ty * 8]);
            float4 m1 = *reinterpret_cast<const float4*>(&Mts[k * CC + ty * 8 + 4]);
            float4 xv = *reinterpret_cast<const float4*>(&Xs[k * 128 + tx * 4]);
            ull mp0 = pk2(m0.x, m0.y), mp1 = pk2(m0.z, m0.w);
            ull mp2 = pk2(m1.x, m1.y), mp3 = pk2(m1.z, m1.w);
            float xa[4] = {xv.x, xv.y, xv.z, xv.w};
#pragma unroll
            for (int j = 0; j < 4; j++) {
                ull xd = pk2(xa[j], xa[j]);
                ffma2(acc[0][j], mp0, xd);
                ffma2(acc[1][j], mp1, xd);
                ffma2(acc[2][j], mp2, xd);
                ffma2(acc[3][j], mp3, xd);
            }
        }
#pragma unroll
        for (int c2 = 0; c2 < 4; c2++) {
            int c = ty * 8 + 2 * c2;
            float cv0 = g_cv[b * CC + c], cv1 = g_cv[b * CC + c + 1];
#pragma unroll
            for (int j = 0; j < 4; j++) {
                float2 v = upk(acc[c2][j]);
                Us[c * 128 + tx * 4 + j]       = fmaxf(v.x + cv0, 0.f);
                Us[(c + 1) * 128 + tx * 4 + j] = fmaxf(v.y + cv1, 0.f);
            }
        }
    }
    __syncthreads();

    // Step B: Y = wo U + bo, masked. 16x16 thread grid, tile 8o x 8t, acc packed along t.
    {
        const int ty = tid >> 4, tx = tid & 15;
        ull acc[8][4];
#pragma unroll
        for (int i = 0; i < 8; i++)
#pragma unroll
            for (int j = 0; j < 4; j++) acc[i][j] = 0ull;
#pragma unroll 4
        for (int k = 0; k < CC; k++) {
            float4 w0 = *reinterpret_cast<const float4*>(&Wts[k * 128 + ty * 8]);
            float4 w1 = *reinterpret_cast<const float4*>(&Wts[k * 128 + ty * 8 + 4]);
            float4 u0 = *reinterpret_cast<const float4*>(&Us[k * 128 + tx * 8]);
            float4 u1 = *reinterpret_cast<const float4*>(&Us[k * 128 + tx * 8 + 4]);
            ull up0 = pk2(u0.x, u0.y), up1 = pk2(u0.z, u0.w);
            ull up2 = pk2(u1.x, u1.y), up3 = pk2(u1.z, u1.w);
            float wa[8] = {w0.x, w0.y, w0.z, w0.w, w1.x, w1.y, w1.z, w1.w};
#pragma unroll
            for (int i = 0; i < 8; i++) {
                ull wd = pk2(wa[i], wa[i]);
                ffma2(acc[i][0], wd, up0);
                ffma2(acc[i][1], wd, up1);
                ffma2(acc[i][2], wd, up2);
                ffma2(acc[i][3], wd, up3);
            }
        }
        const float* mb = mask + (size_t)b * TT + t0 + tx * 8;
        float4 mq0 = *reinterpret_cast<const float4*>(mb);
        float4 mq1 = *reinterpret_cast<const float4*>(mb + 4);
        ull mp0 = pk2(mq0.x, mq0.y), mp1 = pk2(mq0.z, mq0.w);
        ull mp2 = pk2(mq1.x, mq1.y), mp3 = pk2(mq1.z, mq1.w);
        float* yb = y + (size_t)b * DD * TT + t0;
#pragma unroll
        for (int i = 0; i < 8; i++) {
            int o = ty * 8 + i;
            float bov = bo[o];
            ull bod = pk2(bov, bov);
            float2 r0 = upk(mul2(add2(acc[i][0], bod), mp0));
            float2 r1 = upk(mul2(add2(acc[i][1], bod), mp1));
            float2 r2 = upk(mul2(add2(acc[i][2], bod), mp2));
            float2 r3 = upk(mul2(add2(acc[i][3], bod), mp3));
            float4 o0 = {r0.x, r0.y, r1.x, r1.y};
            float4 o1 = {r2.x, r2.y, r3.x, r3.y};
            float* row = &yb[(size_t)o * TT + tx * 8];
            *reinterpret_cast<float4*>(row)     = o0;
            *reinterpret_cast<float4*>(row + 4) = o1;
        }
    }
}

static const int SMEM_K2C = (DD * KPAD + CC * KPAD * 2 + 8 * KPAD * 2 + 8 * CC +
                             DD + 3 * CC + 16) * (int)sizeof(float);
static const int SMEM_K3  = (DD * 128 + CC * 128 + DD * CC + CC * DD) * (int)sizeof(float);

extern "C" void kernel_launch(void* const* d_in, const int* in_sizes, int n_in,
                              void* d_out, int out_size) {
    const float* x1   = (const float*)d_in[0];
    // d_in[1] = x2 (unused in encoder stage)
    const float* mask = (const float*)d_in[2];
    const float* wq   = (const float*)d_in[3];
    const float* bq   = (const float*)d_in[4];
    const float* wk   = (const float*)d_in[5];
    const float* bk   = (const float*)d_in[6];
    const float* wv   = (const float*)d_in[7];
    const float* bv   = (const float*)d_in[8];
    const float* we   = (const float*)d_in[9];
    const float* be   = (const float*)d_in[10];
    const float* wf   = (const float*)d_in[11];
    const float* bf   = (const float*)d_in[12];
    const float* wo   = (const float*)d_in[13];
    const float* bo   = (const float*)d_in[14];
    float* y = (float*)d_out;

    cudaFuncSetAttribute(k2c_attn, cudaFuncAttributeMaxDynamicSharedMemorySize, SMEM_K2C);
    cudaFuncSetAttribute(k3_out,   cudaFuncAttributeMaxDynamicSharedMemorySize, SMEM_K3);

    void *pG = nullptr, *ps = nullptr;
    cudaGetSymbolAddress(&pG, g_G);
    cudaGetSymbolAddress(&ps, g_s);
    cudaMemsetAsync(pG, 0, BB * DD * DD * sizeof(float));
    cudaMemsetAsync(ps, 0, BB * DD * sizeof(float));

    k1_gram<<<dim3(32, 8), 256>>>(x1);
    k2a_weights<<<16, 256>>>(we, wk, bk, be, wf, wv, bv, bf, wo);
    k2c_attn<<<dim3(8, 8), 256, SMEM_K2C>>>(wq, bq);
    k3_out<<<dim3(256, 8), 256, SMEM_K3>>>(x1, mask, bo, y);
}